// round 12
// baseline (speedup 1.0000x reference)
#include <cuda_runtime.h>
#include <cstdint>

#define B_SZ 512
#define D_SZ 1024
#define P_SZ 16
#define N_SZ 128
#define ALPHA_F 0.8f
#define NROWS 145                       // per batch: row 0 = tgt, 1..16 = rel, 17..144 = irr
#define TOTAL_ROWS (B_SZ * NROWS)       // 74240
#define TPB 128
#define NWARPS 4
#define BLOCKS_PER_SM 6
#define ROW_BYTES 4096                  // 1024 fp32

__device__ float g_posb[B_SZ];          // zero at load; finisher resets each run
__device__ float g_negb[B_SZ];
__device__ float g_diag[B_SZ];
__device__ unsigned int g_cnt[B_SZ];    // per-batch arrival counters
__device__ float g_loss = 0.f;
__device__ unsigned int g_count = 0;

__device__ __forceinline__ uint32_t smem_u32(const void* p) {
    uint32_t a;
    asm("{ .reg .u64 t; cvta.to.shared.u64 t, %1; cvt.u32.u64 %0, t; }"
        : "=r"(a) : "l"(p));
    return a;
}
__device__ __forceinline__ void mbar_init(uint32_t mbar, uint32_t count) {
    asm volatile("mbarrier.init.shared.b64 [%0], %1;" :: "r"(mbar), "r"(count) : "memory");
}
__device__ __forceinline__ void mbar_expect_tx(uint32_t mbar, uint32_t bytes) {
    asm volatile("mbarrier.arrive.expect_tx.shared.b64 _, [%0], %1;"
                 :: "r"(mbar), "r"(bytes) : "memory");
}
__device__ __forceinline__ void tma_row(uint32_t smem_dst, const float* gmem_src, uint32_t mbar) {
    asm volatile("cp.async.bulk.shared::cta.global.mbarrier::complete_tx::bytes "
                 "[%0], [%1], %2, [%3];"
                 :: "r"(smem_dst), "l"(gmem_src), "r"((uint32_t)ROW_BYTES), "r"(mbar)
                 : "memory");
}
__device__ __forceinline__ void mbar_wait(uint32_t mbar, uint32_t parity) {
    uint32_t done;
    asm volatile(
        "{\n\t.reg .pred p;\n\t"
        "mbarrier.try_wait.parity.acquire.cta.shared::cta.b64 p, [%1], %2;\n\t"
        "selp.b32 %0, 1, 0, p;\n\t}"
        : "=r"(done) : "r"(mbar), "r"(parity) : "memory");
    if (!done) {
        asm volatile(
            "{\n\t.reg .pred P1;\n\t"
            "W_%=:\n\t"
            "mbarrier.try_wait.parity.acquire.cta.shared::cta.b64 P1, [%0], %1, 0x989680;\n\t"
            "@P1 bra.uni D_%=;\n\t"
            "bra.uni W_%=;\n\t"
            "D_%=:\n\t}"
            :: "r"(mbar), "r"(parity) : "memory");
    }
}
__device__ __forceinline__ unsigned atom_add_acqrel(unsigned* p, unsigned v) {
    unsigned old;
    asm volatile("atom.acq_rel.gpu.global.add.u32 %0, [%1], %2;"
                 : "=r"(old) : "l"(p), "r"(v) : "memory");
    return old;
}

__device__ __forceinline__ const float*
row_ptr_br(const float* __restrict__ tgt, const float* __restrict__ rel,
           const float* __restrict__ irr, int b, int r)
{
    if (r == 0)         return tgt + (size_t)b * D_SZ;
    else if (r <= P_SZ) return rel + ((size_t)b * P_SZ + (r - 1)) * D_SZ;
    else                return irr + ((size_t)b * N_SZ + (r - 1 - P_SZ)) * D_SZ;
}

__device__ __forceinline__ void
load_sreg(const float* __restrict__ src, int b, int lane,
          float4 (&sreg)[8], float& inv_src)
{
    const float4* sv = reinterpret_cast<const float4*>(src + (size_t)b * D_SZ);
    float ss = 0.f;
    #pragma unroll
    for (int j = 0; j < 8; j++) {
        sreg[j] = __ldg(&sv[j * 32 + lane]);
        ss += sreg[j].x * sreg[j].x + sreg[j].y * sreg[j].y
            + sreg[j].z * sreg[j].z + sreg[j].w * sreg[j].w;
    }
    #pragma unroll
    for (int o = 16; o > 0; o >>= 1) ss += __shfl_xor_sync(0xFFFFFFFFu, ss, o);
    inv_src = rsqrtf(fmaxf(ss, 1e-24f));
}

// lane0-only: flush partials for batch b; if this warp is the last contributor,
// compute the batch's loss term inline and fold it into g_loss.
__device__ __forceinline__ void
flush_batch(int b, float pos, float neg, int nw)
{
    atomicAdd(&g_posb[b], pos);
    atomicAdd(&g_negb[b], neg);

    // warps whose contiguous slice intersects batch b: w(x) = ((x+1)*nw - 1)/T
    const long long s = (long long)b * NROWS;
    const int w_first = (int)(((s + 1) * nw - 1) / TOTAL_ROWS);
    const int w_last  = (int)(((s + NROWS) * nw - 1) / TOTAL_ROWS);
    const unsigned need = (unsigned)(w_last - w_first + 1);

    unsigned old = atom_add_acqrel(&g_cnt[b], 1u);
    if (old == need - 1u) {               // last contributor: finish batch b now
        float ps = __ldcg(&g_posb[b]);
        float ns = __ldcg(&g_negb[b]);
        float dg = __ldcg(&g_diag[b]);
        float pos_score = 1.f + ps;
        float lb = -(ALPHA_F * dg +
                     (1.f - ALPHA_F) * (__logf(pos_score) - __logf(pos_score + ns)));
        g_posb[b] = 0.f;                   // reset for next graph replay
        g_negb[b] = 0.f;
        g_cnt[b]  = 0u;
        atomicAdd(&g_loss, lb);
    }
}

__global__ void __launch_bounds__(TPB, BLOCKS_PER_SM)
contrastive_loss_kernel(const float* __restrict__ src,
                        const float* __restrict__ tgt,
                        const float* __restrict__ rel,
                        const float* __restrict__ irr,
                        float* __restrict__ out,
                        int nblocks)
{
    __shared__ __align__(16) float4 s_buf[NWARPS][2][ROW_BYTES / 16]; // 32 KB
    __shared__ __align__(8)  unsigned long long s_mbar[NWARPS][2];
    __shared__ int s_last;

    const int tid  = threadIdx.x;
    const int wid  = tid >> 5;
    const int lane = tid & 31;

    const uint32_t mb0 = smem_u32(&s_mbar[wid][0]);
    const uint32_t mb1 = smem_u32(&s_mbar[wid][1]);
    const uint32_t sb0 = smem_u32(&s_buf[wid][0][0]);
    const uint32_t sb1 = smem_u32(&s_buf[wid][1][0]);

    if (lane == 0) {
        mbar_init(mb0, 1);
        mbar_init(mb1, 1);
        asm volatile("fence.mbarrier_init.release.cluster;" ::: "memory");
    }
    __syncwarp();

    // ---- contiguous slice of the flat row space for this warp ----
    const int nw   = nblocks * NWARPS;
    const int wgid = blockIdx.x * NWARPS + wid;
    const int lo = (int)(((long long)wgid * TOTAL_ROWS) / nw);
    const int hi = (int)(((long long)(wgid + 1) * TOTAL_ROWS) / nw);

    // ---- prime pipeline once for the whole slice ----
    if (lane == 0) {
        if (lo < hi) {
            int pb = lo / NROWS, pr = lo - pb * NROWS;
            mbar_expect_tx(mb0, ROW_BYTES);
            tma_row(sb0, row_ptr_br(tgt, rel, irr, pb, pr), mb0);
        }
        if (lo + 1 < hi) {
            int pb = (lo + 1) / NROWS, pr = (lo + 1) - pb * NROWS;
            mbar_expect_tx(mb1, ROW_BYTES);
            tma_row(sb1, row_ptr_br(tgt, rel, irr, pb, pr), mb1);
        }
    }

    int b = lo / NROWS;
    int r = lo - b * NROWS;
    float4 sreg[8];
    float inv_src;
    load_sreg(src, b, lane, sreg, inv_src);

    float pos = 0.f, neg = 0.f;
    uint32_t ph0 = 0, ph1 = 0;

    for (int g = lo; g < hi; g++) {
        if (r == NROWS) {                  // crossed into next batch row
            if (lane == 0) {
                flush_batch(b, pos, neg, nw);
                pos = 0.f; neg = 0.f;
            }
            b++; r = 0;
            load_sreg(src, b, lane, sreg, inv_src);
        }

        const int k = (g - lo) & 1;
        if (k == 0) { mbar_wait(mb0, ph0); ph0 ^= 1u; }
        else        { mbar_wait(mb1, ph1); ph1 ^= 1u; }

        const float4* rv = &s_buf[wid][k][0];
        float dot = 0.f, rss = 0.f;
        #pragma unroll
        for (int j = 0; j < 8; j++) {
            float4 v = rv[j * 32 + lane];
            dot += v.x * sreg[j].x + v.y * sreg[j].y + v.z * sreg[j].z + v.w * sreg[j].w;
            rss += v.x * v.x + v.y * v.y + v.z * v.z + v.w * v.w;
        }

        // refill this stage with row g+2 (all lanes finished reading it)
        if (lane == 0 && g + 2 < hi) {
            int r2 = r + 2, b2 = b;
            if (r2 >= NROWS) { r2 -= NROWS; b2++; }
            const uint32_t mb = k ? mb1 : mb0;
            const uint32_t sb = k ? sb1 : sb0;
            mbar_expect_tx(mb, ROW_BYTES);
            tma_row(sb, row_ptr_br(tgt, rel, irr, b2, r2), mb);
        }

        #pragma unroll
        for (int o = 16; o > 0; o >>= 1) {
            dot += __shfl_xor_sync(0xFFFFFFFFu, dot, o);
            rss += __shfl_xor_sync(0xFFFFFFFFu, rss, o);
        }
        if (lane == 0) {
            float c = dot * inv_src * rsqrtf(fmaxf(rss, 1e-24f));
            if (r == 0)            g_diag[b] = c;          // tgt row
            else if (r <= P_SZ)    pos += __expf(c);
            else                   neg += __expf(c);
        }
        r++;
    }

    if (lane == 0)
        flush_batch(b, pos, neg, nw);       // final (possibly partial) batch
    __syncthreads();

    if (tid == 0) {
        unsigned old = atom_add_acqrel(&g_count, 1u);
        s_last = (old == (unsigned)nblocks - 1u);
    }
    __syncthreads();

    // ---- last block: O(1) epilogue ----
    if (s_last && tid == 0) {
        out[0] = __ldcg(&g_loss) * (1.0f / (float)B_SZ);
        g_loss  = 0.f;                      // reset for next graph replay
        g_count = 0u;
    }
}

extern "C" void kernel_launch(void* const* d_in, const int* in_sizes, int n_in,
                              void* d_out, int out_size)
{
    const float* src = (const float*)d_in[0];   // [B, D]
    const float* tgt = (const float*)d_in[1];   // [B, D]
    const float* rel = (const float*)d_in[2];   // [B, P, D]
    const float* irr = (const float*)d_in[3];   // [B, N, D]
    float* out = (float*)d_out;

    int sms = 148;
    cudaDeviceGetAttribute(&sms, cudaDevAttrMultiProcessorCount, 0);
    const int nblocks = sms * BLOCKS_PER_SM;    // exactly one wave

    contrastive_loss_kernel<<<nblocks, TPB>>>(src, tgt, rel, irr, out, nblocks);
}

// round 13
// speedup vs baseline: 1.0865x; 1.0865x over previous
#include <cuda_runtime.h>
#include <cstdint>

#define B_SZ 512
#define D_SZ 1024
#define P_SZ 16
#define N_SZ 128
#define ALPHA_F 0.8f
#define NROWS 145                       // per batch: row 0 = tgt, 1..16 = rel, 17..144 = irr
#define TOTAL_ROWS (B_SZ * NROWS)       // 74240
#define TPB 128
#define NWARPS 4
#define BLOCKS_PER_SM 6
#define ROW_BYTES 4096                  // 1024 fp32
#define CH 4                            // rows per stolen chunk
#define NCHUNK (TOTAL_ROWS / CH)        // 18560

__device__ float g_posb[B_SZ];          // zero at load; epilogue resets each run
__device__ float g_negb[B_SZ];
__device__ float g_diag[B_SZ];
__device__ unsigned int g_chunk = 0;    // work-steal counter
__device__ unsigned int g_count = 0;    // block completion counter

__device__ __forceinline__ uint32_t smem_u32(const void* p) {
    uint32_t a;
    asm("{ .reg .u64 t; cvta.to.shared.u64 t, %1; cvt.u32.u64 %0, t; }"
        : "=r"(a) : "l"(p));
    return a;
}
__device__ __forceinline__ void mbar_init(uint32_t mbar, uint32_t count) {
    asm volatile("mbarrier.init.shared.b64 [%0], %1;" :: "r"(mbar), "r"(count) : "memory");
}
__device__ __forceinline__ void mbar_expect_tx(uint32_t mbar, uint32_t bytes) {
    asm volatile("mbarrier.arrive.expect_tx.shared.b64 _, [%0], %1;"
                 :: "r"(mbar), "r"(bytes) : "memory");
}
__device__ __forceinline__ void tma_row(uint32_t smem_dst, const float* gmem_src, uint32_t mbar) {
    asm volatile("cp.async.bulk.shared::cta.global.mbarrier::complete_tx::bytes "
                 "[%0], [%1], %2, [%3];"
                 :: "r"(smem_dst), "l"(gmem_src), "r"((uint32_t)ROW_BYTES), "r"(mbar)
                 : "memory");
}
__device__ __forceinline__ void mbar_wait(uint32_t mbar, uint32_t parity) {
    uint32_t done;
    asm volatile(
        "{\n\t.reg .pred p;\n\t"
        "mbarrier.try_wait.parity.acquire.cta.shared::cta.b64 p, [%1], %2;\n\t"
        "selp.b32 %0, 1, 0, p;\n\t}"
        : "=r"(done) : "r"(mbar), "r"(parity) : "memory");
    if (!done) {
        asm volatile(
            "{\n\t.reg .pred P1;\n\t"
            "W_%=:\n\t"
            "mbarrier.try_wait.parity.acquire.cta.shared::cta.b64 P1, [%0], %1, 0x989680;\n\t"
            "@P1 bra.uni D_%=;\n\t"
            "bra.uni W_%=;\n\t"
            "D_%=:\n\t}"
            :: "r"(mbar), "r"(parity) : "memory");
    }
}
__device__ __forceinline__ unsigned atom_add_acqrel(unsigned* p, unsigned v) {
    unsigned old;
    asm volatile("atom.acq_rel.gpu.global.add.u32 %0, [%1], %2;"
                 : "=r"(old) : "l"(p), "r"(v) : "memory");
    return old;
}

__device__ __forceinline__ const float*
row_ptr_g(const float* __restrict__ tgt, const float* __restrict__ rel,
          const float* __restrict__ irr, int g)
{
    const int b = g / NROWS;
    const int r = g - b * NROWS;
    if (r == 0)         return tgt + (size_t)b * D_SZ;
    else if (r <= P_SZ) return rel + ((size_t)b * P_SZ + (r - 1)) * D_SZ;
    else                return irr + ((size_t)b * N_SZ + (r - 1 - P_SZ)) * D_SZ;
}

__device__ __forceinline__ void
load_sreg(const float* __restrict__ src, int b, int lane,
          float4 (&sreg)[8], float& inv_src)
{
    const float4* sv = reinterpret_cast<const float4*>(src + (size_t)b * D_SZ);
    float ss = 0.f;
    #pragma unroll
    for (int j = 0; j < 8; j++) {
        sreg[j] = __ldg(&sv[j * 32 + lane]);
        ss += sreg[j].x * sreg[j].x + sreg[j].y * sreg[j].y
            + sreg[j].z * sreg[j].z + sreg[j].w * sreg[j].w;
    }
    #pragma unroll
    for (int o = 16; o > 0; o >>= 1) ss += __shfl_xor_sync(0xFFFFFFFFu, ss, o);
    inv_src = rsqrtf(fmaxf(ss, 1e-24f));
}

// warp-uniform chunk steal: lane0 atomics, broadcast to all lanes
__device__ __forceinline__ int steal_chunk(int lane) {
    unsigned idx = 0;
    if (lane == 0) idx = atomicAdd(&g_chunk, 1u);
    idx = __shfl_sync(0xFFFFFFFFu, idx, 0);
    return (idx < NCHUNK) ? (int)(idx * CH) : -1;   // base row or -1
}

__global__ void __launch_bounds__(TPB, BLOCKS_PER_SM)
contrastive_loss_kernel(const float* __restrict__ src,
                        const float* __restrict__ tgt,
                        const float* __restrict__ rel,
                        const float* __restrict__ irr,
                        float* __restrict__ out,
                        int nblocks)
{
    __shared__ __align__(16) float4 s_buf[NWARPS][2][ROW_BYTES / 16]; // 32 KB
    __shared__ __align__(8)  unsigned long long s_mbar[NWARPS][2];
    __shared__ float s_red[NWARPS];
    __shared__ int   s_last;

    const int tid  = threadIdx.x;
    const int wid  = tid >> 5;
    const int lane = tid & 31;

    const uint32_t mb[2] = { smem_u32(&s_mbar[wid][0]), smem_u32(&s_mbar[wid][1]) };
    const uint32_t sb[2] = { smem_u32(&s_buf[wid][0][0]), smem_u32(&s_buf[wid][1][0]) };

    if (lane == 0) {
        mbar_init(mb[0], 1);
        mbar_init(mb[1], 1);
        asm volatile("fence.mbarrier_init.release.cluster;" ::: "memory");
    }
    __syncwarp();

    // ---- steal first two chunks; prime depth-2 ring with rows c0+0, c0+1 ----
    int c0 = steal_chunk(lane);
    int c1 = steal_chunk(lane);

    if (lane == 0 && c0 >= 0) {
        mbar_expect_tx(mb[0], ROW_BYTES);
        tma_row(sb[0], row_ptr_g(tgt, rel, irr, c0), mb[0]);
        mbar_expect_tx(mb[1], ROW_BYTES);
        tma_row(sb[1], row_ptr_g(tgt, rel, irr, c0 + 1), mb[1]);
    }

    float4 sreg[8];
    float inv_src = 0.f;
    int b = -1;                           // sentinel: force sreg load on first row
    float pos = 0.f, neg = 0.f;

    uint32_t ph[2] = { 0u, 0u };
    int t = 0;                            // buffer toggle
    int i = 0;                            // index within current chunk

    while (c0 >= 0) {
        const int g = c0 + i;
        const int bn = g / NROWS;
        const int r  = g - bn * NROWS;

        if (bn != b) {                    // batch change: flush + reload src regs
            if (lane == 0 && b >= 0) {
                atomicAdd(&g_posb[b], pos);
                atomicAdd(&g_negb[b], neg);
            }
            pos = 0.f; neg = 0.f;
            b = bn;
            load_sreg(src, b, lane, sreg, inv_src);
        }

        mbar_wait(mb[t], ph[t]); ph[t] ^= 1u;

        const float4* rv = &s_buf[wid][t][0];
        float dot = 0.f, rss = 0.f;
        #pragma unroll
        for (int j = 0; j < 8; j++) {
            float4 v = rv[j * 32 + lane];
            dot += v.x * sreg[j].x + v.y * sreg[j].y + v.z * sreg[j].z + v.w * sreg[j].w;
            rss += v.x * v.x + v.y * v.y + v.z * v.z + v.w * v.w;
        }

        // refill buffer t with row (i+2) of the cur+next chunk sequence
        if (lane == 0) {
            const int j2 = i + 2;
            int gp = -1;
            if (j2 < CH)        gp = c0 + j2;
            else if (c1 >= 0)   gp = c1 + (j2 - CH);
            if (gp >= 0) {
                mbar_expect_tx(mb[t], ROW_BYTES);
                tma_row(sb[t], row_ptr_g(tgt, rel, irr, gp), mb[t]);
            }
        }

        #pragma unroll
        for (int o = 16; o > 0; o >>= 1) {
            dot += __shfl_xor_sync(0xFFFFFFFFu, dot, o);
            rss += __shfl_xor_sync(0xFFFFFFFFu, rss, o);
        }
        if (lane == 0) {
            float c = dot * inv_src * rsqrtf(fmaxf(rss, 1e-24f));
            if (r == 0)            g_diag[b] = c;          // tgt row
            else if (r <= P_SZ)    pos += __expf(c);
            else                   neg += __expf(c);
        }

        t ^= 1;
        if (++i == CH) {                  // chunk done: advance, pre-steal next
            c0 = c1;
            i = 0;
            c1 = steal_chunk(lane);
        }
    }

    if (lane == 0 && b >= 0) {
        atomicAdd(&g_posb[b], pos);
        atomicAdd(&g_negb[b], neg);
    }
    __syncthreads();

    if (tid == 0) {
        unsigned old = atom_add_acqrel(&g_count, 1u);
        s_last = (old == (unsigned)nblocks - 1u);
    }
    __syncthreads();

    // ---- last block: parallel final loss over 512 batch rows + resets ----
    if (s_last) {
        float acc = 0.f;
        #pragma unroll
        for (int it = 0; it < B_SZ / TPB; it++) {
            int bb = it * TPB + tid;
            float ps = __ldcg(&g_posb[bb]);
            float ns = __ldcg(&g_negb[bb]);
            float dg = __ldcg(&g_diag[bb]);
            float pos_score = 1.f + ps;
            float lp = __logf(pos_score);
            float ln = __logf(pos_score + ns);
            acc += -(ALPHA_F * dg + (1.f - ALPHA_F) * (lp - ln));
            g_posb[bb] = 0.f;             // reset for next graph replay
            g_negb[bb] = 0.f;
        }
        #pragma unroll
        for (int o = 16; o > 0; o >>= 1) acc += __shfl_xor_sync(0xFFFFFFFFu, acc, o);
        if (lane == 0) s_red[wid] = acc;
        __syncthreads();
        if (tid == 0) {
            out[0] = (s_red[0] + s_red[1] + s_red[2] + s_red[3]) * (1.0f / (float)B_SZ);
            g_chunk = 0u;                 // reset work-steal counter
            g_count = 0u;
        }
    }
}

extern "C" void kernel_launch(void* const* d_in, const int* in_sizes, int n_in,
                              void* d_out, int out_size)
{
    const float* src = (const float*)d_in[0];   // [B, D]
    const float* tgt = (const float*)d_in[1];   // [B, D]
    const float* rel = (const float*)d_in[2];   // [B, P, D]
    const float* irr = (const float*)d_in[3];   // [B, N, D]
    float* out = (float*)d_out;

    int sms = 148;
    cudaDeviceGetAttribute(&sms, cudaDevAttrMultiProcessorCount, 0);
    const int nblocks = sms * BLOCKS_PER_SM;    // exactly one wave

    contrastive_loss_kernel<<<nblocks, TPB>>>(src, tgt, rel, irr, out, nblocks);
}

// round 14
// speedup vs baseline: 1.1268x; 1.0371x over previous
#include <cuda_runtime.h>
#include <cstdint>

#define B_SZ 512
#define D_SZ 1024
#define P_SZ 16
#define N_SZ 128
#define ALPHA_F 0.8f
#define NROWS 145                       // per batch: row 0 = tgt, 1..16 = rel, 17..144 = irr
#define TOTAL_ROWS (B_SZ * NROWS)       // 74240
#define TPB 128
#define NWARPS 4
#define BLOCKS_PER_SM 6
#define ROW_BYTES 4096                  // 1024 fp32

__device__ float g_posb[B_SZ];          // zero at load; epilogue resets each run
__device__ float g_negb[B_SZ];
__device__ float g_diag[B_SZ];
__device__ unsigned int g_count = 0;

__device__ __forceinline__ uint32_t smem_u32(const void* p) {
    uint32_t a;
    asm("{ .reg .u64 t; cvta.to.shared.u64 t, %1; cvt.u32.u64 %0, t; }"
        : "=r"(a) : "l"(p));
    return a;
}
__device__ __forceinline__ void mbar_init(uint32_t mbar, uint32_t count) {
    asm volatile("mbarrier.init.shared.b64 [%0], %1;" :: "r"(mbar), "r"(count) : "memory");
}
__device__ __forceinline__ void mbar_expect_tx(uint32_t mbar, uint32_t bytes) {
    asm volatile("mbarrier.arrive.expect_tx.shared.b64 _, [%0], %1;"
                 :: "r"(mbar), "r"(bytes) : "memory");
}
__device__ __forceinline__ void tma_row(uint32_t smem_dst, const float* gmem_src, uint32_t mbar) {
    asm volatile("cp.async.bulk.shared::cta.global.mbarrier::complete_tx::bytes "
                 "[%0], [%1], %2, [%3];"
                 :: "r"(smem_dst), "l"(gmem_src), "r"((uint32_t)ROW_BYTES), "r"(mbar)
                 : "memory");
}
__device__ __forceinline__ void mbar_wait(uint32_t mbar, uint32_t parity) {
    uint32_t done;
    asm volatile(
        "{\n\t.reg .pred p;\n\t"
        "mbarrier.try_wait.parity.acquire.cta.shared::cta.b64 p, [%1], %2;\n\t"
        "selp.b32 %0, 1, 0, p;\n\t}"
        : "=r"(done) : "r"(mbar), "r"(parity) : "memory");
    if (!done) {
        asm volatile(
            "{\n\t.reg .pred P1;\n\t"
            "W_%=:\n\t"
            "mbarrier.try_wait.parity.acquire.cta.shared::cta.b64 P1, [%0], %1, 0x989680;\n\t"
            "@P1 bra.uni D_%=;\n\t"
            "bra.uni W_%=;\n\t"
            "D_%=:\n\t}"
            :: "r"(mbar), "r"(parity) : "memory");
    }
}
__device__ __forceinline__ unsigned atom_add_acqrel(unsigned* p, unsigned v) {
    unsigned old;
    asm volatile("atom.acq_rel.gpu.global.add.u32 %0, [%1], %2;"
                 : "=r"(old) : "l"(p), "r"(v) : "memory");
    return old;
}

__device__ __forceinline__ const float*
row_ptr_br(const float* __restrict__ tgt, const float* __restrict__ rel,
           const float* __restrict__ irr, int b, int r)
{
    if (r == 0)         return tgt + (size_t)b * D_SZ;
    else if (r <= P_SZ) return rel + ((size_t)b * P_SZ + (r - 1)) * D_SZ;
    else                return irr + ((size_t)b * N_SZ + (r - 1 - P_SZ)) * D_SZ;
}

__device__ __forceinline__ void
load_sreg(const float* __restrict__ src, int b, int lane,
          float4 (&sreg)[8], float& inv_src)
{
    const float4* sv = reinterpret_cast<const float4*>(src + (size_t)b * D_SZ);
    float ss = 0.f;
    #pragma unroll
    for (int j = 0; j < 8; j++) {
        sreg[j] = __ldg(&sv[j * 32 + lane]);
        ss += sreg[j].x * sreg[j].x + sreg[j].y * sreg[j].y
            + sreg[j].z * sreg[j].z + sreg[j].w * sreg[j].w;
    }
    #pragma unroll
    for (int o = 16; o > 0; o >>= 1) ss += __shfl_xor_sync(0xFFFFFFFFu, ss, o);
    inv_src = rsqrtf(fmaxf(ss, 1e-24f));
}

__global__ void __launch_bounds__(TPB, BLOCKS_PER_SM)
contrastive_loss_kernel(const float* __restrict__ src,
                        const float* __restrict__ tgt,
                        const float* __restrict__ rel,
                        const float* __restrict__ irr,
                        float* __restrict__ out,
                        int nblocks)
{
    __shared__ __align__(16) float4 s_buf[NWARPS][2][ROW_BYTES / 16]; // 32 KB
    __shared__ __align__(8)  unsigned long long s_mbar[NWARPS][2];
    __shared__ float s_red[NWARPS];
    __shared__ int   s_last;

    const int tid  = threadIdx.x;
    const int wid  = tid >> 5;
    const int lane = tid & 31;

    const uint32_t mb[2] = { smem_u32(&s_mbar[wid][0]), smem_u32(&s_mbar[wid][1]) };
    const uint32_t sb[2] = { smem_u32(&s_buf[wid][0][0]), smem_u32(&s_buf[wid][1][0]) };

    if (lane == 0) {
        mbar_init(mb[0], 1);
        mbar_init(mb[1], 1);
        asm volatile("fence.mbarrier_init.release.cluster;" ::: "memory");
    }
    __syncwarp();

    // ---- contiguous slice of the flat row space for this warp (R11) ----
    const int nw   = nblocks * NWARPS;
    const int wgid = blockIdx.x * NWARPS + wid;
    const int lo = (int)(((long long)wgid * TOTAL_ROWS) / nw);
    const int hi = (int)(((long long)(wgid + 1) * TOTAL_ROWS) / nw);

    // ---- prime pipeline once for the whole slice ----
    if (lane == 0) {
        if (lo < hi) {
            int pb = lo / NROWS, pr = lo - pb * NROWS;
            mbar_expect_tx(mb[0], ROW_BYTES);
            tma_row(sb[0], row_ptr_br(tgt, rel, irr, pb, pr), mb[0]);
        }
        if (lo + 1 < hi) {
            int pb = (lo + 1) / NROWS, pr = (lo + 1) - pb * NROWS;
            mbar_expect_tx(mb[1], ROW_BYTES);
            tma_row(sb[1], row_ptr_br(tgt, rel, irr, pb, pr), mb[1]);
        }
    }

    int b = lo / NROWS;
    int r = lo - b * NROWS;
    float4 sreg[8];
    float inv_src;
    load_sreg(src, b, lane, sreg, inv_src);

    float pos = 0.f, neg = 0.f;
    uint32_t ph[2] = { 0u, 0u };

    // invariant: row g is in buffer k=(g-lo)&1; refill g+2 into buffer k.
    int g = lo;
    while (g < hi) {
        if (r == NROWS) {                  // crossed into next batch row
            if (lane == 0) {
                atomicAdd(&g_posb[b], pos);
                atomicAdd(&g_negb[b], neg);
                pos = 0.f; neg = 0.f;
            }
            b++; r = 0;
            load_sreg(src, b, lane, sreg, inv_src);
        }

        const int k = (g - lo) & 1;
        const bool pair = (g + 1 < hi) && (r + 1 < NROWS);   // both rows same batch

        // ---- row g (buffer k) ----
        mbar_wait(mb[k], ph[k]); ph[k] ^= 1u;
        const float4* rv0 = &s_buf[wid][k][0];
        float dot0 = 0.f, rss0 = 0.f;
        #pragma unroll
        for (int j = 0; j < 8; j++) {
            float4 v = rv0[j * 32 + lane];
            dot0 += v.x * sreg[j].x + v.y * sreg[j].y + v.z * sreg[j].z + v.w * sreg[j].w;
            rss0 += v.x * v.x + v.y * v.y + v.z * v.z + v.w * v.w;
        }
        if (lane == 0 && g + 2 < hi) {
            int r2 = r + 2, b2 = b;
            if (r2 >= NROWS) { r2 -= NROWS; b2++; }
            mbar_expect_tx(mb[k], ROW_BYTES);
            tma_row(sb[k], row_ptr_br(tgt, rel, irr, b2, r2), mb[k]);
        }

        if (pair) {
            // ---- row g+1 (buffer k^1), same sreg ----
            const int k1 = k ^ 1;
            mbar_wait(mb[k1], ph[k1]); ph[k1] ^= 1u;
            const float4* rv1 = &s_buf[wid][k1][0];
            float dot1 = 0.f, rss1 = 0.f;
            #pragma unroll
            for (int j = 0; j < 8; j++) {
                float4 v = rv1[j * 32 + lane];
                dot1 += v.x * sreg[j].x + v.y * sreg[j].y + v.z * sreg[j].z + v.w * sreg[j].w;
                rss1 += v.x * v.x + v.y * v.y + v.z * v.z + v.w * v.w;
            }
            if (lane == 0 && g + 3 < hi) {
                int r3 = r + 3, b3 = b;
                if (r3 >= NROWS) { r3 -= NROWS; b3++; }
                mbar_expect_tx(mb[k1], ROW_BYTES);
                tma_row(sb[k1], row_ptr_br(tgt, rel, irr, b3, r3), mb[k1]);
            }

            // one combined butterfly window for 2 rows (4 interleaved chains)
            #pragma unroll
            for (int o = 16; o > 0; o >>= 1) {
                dot0 += __shfl_xor_sync(0xFFFFFFFFu, dot0, o);
                rss0 += __shfl_xor_sync(0xFFFFFFFFu, rss0, o);
                dot1 += __shfl_xor_sync(0xFFFFFFFFu, dot1, o);
                rss1 += __shfl_xor_sync(0xFFFFFFFFu, rss1, o);
            }
            if (lane == 0) {
                float c0 = dot0 * inv_src * rsqrtf(fmaxf(rss0, 1e-24f));
                float c1 = dot1 * inv_src * rsqrtf(fmaxf(rss1, 1e-24f));
                if (r == 0)            g_diag[b] = c0;
                else if (r <= P_SZ)    pos += __expf(c0);
                else                   neg += __expf(c0);
                if (r + 1 <= P_SZ)     pos += __expf(c1);   // r+1 >= 1 always
                else                   neg += __expf(c1);
            }
            g += 2; r += 2;
        } else {
            #pragma unroll
            for (int o = 16; o > 0; o >>= 1) {
                dot0 += __shfl_xor_sync(0xFFFFFFFFu, dot0, o);
                rss0 += __shfl_xor_sync(0xFFFFFFFFu, rss0, o);
            }
            if (lane == 0) {
                float c0 = dot0 * inv_src * rsqrtf(fmaxf(rss0, 1e-24f));
                if (r == 0)            g_diag[b] = c0;
                else if (r <= P_SZ)    pos += __expf(c0);
                else                   neg += __expf(c0);
            }
            g += 1; r += 1;
        }
    }

    if (lane == 0) {
        atomicAdd(&g_posb[b], pos);
        atomicAdd(&g_negb[b], neg);
    }
    __syncthreads();

    if (tid == 0) {
        unsigned old = atom_add_acqrel(&g_count, 1u);
        s_last = (old == (unsigned)nblocks - 1u);
    }
    __syncthreads();

    // ---- last block: parallel final loss over 512 batch rows + resets ----
    if (s_last) {
        float acc = 0.f;
        #pragma unroll
        for (int it = 0; it < B_SZ / TPB; it++) {
            int bb = it * TPB + tid;
            float ps = __ldcg(&g_posb[bb]);
            float ns = __ldcg(&g_negb[bb]);
            float dg = __ldcg(&g_diag[bb]);
            float pos_score = 1.f + ps;
            float lp = __logf(pos_score);
            float ln = __logf(pos_score + ns);
            acc += -(ALPHA_F * dg + (1.f - ALPHA_F) * (lp - ln));
            g_posb[bb] = 0.f;             // reset for next graph replay
            g_negb[bb] = 0.f;
        }
        #pragma unroll
        for (int o = 16; o > 0; o >>= 1) acc += __shfl_xor_sync(0xFFFFFFFFu, acc, o);
        if (lane == 0) s_red[wid] = acc;
        __syncthreads();
        if (tid == 0) {
            out[0] = (s_red[0] + s_red[1] + s_red[2] + s_red[3]) * (1.0f / (float)B_SZ);
            g_count = 0u;
        }
    }
}

extern "C" void kernel_launch(void* const* d_in, const int* in_sizes, int n_in,
                              void* d_out, int out_size)
{
    const float* src = (const float*)d_in[0];   // [B, D]
    const float* tgt = (const float*)d_in[1];   // [B, D]
    const float* rel = (const float*)d_in[2];   // [B, P, D]
    const float* irr = (const float*)d_in[3];   // [B, N, D]
    float* out = (float*)d_out;

    int sms = 148;
    cudaDeviceGetAttribute(&sms, cudaDevAttrMultiProcessorCount, 0);
    const int nblocks = sms * BLOCKS_PER_SM;    // exactly one wave

    contrastive_loss_kernel<<<nblocks, TPB>>>(src, tgt, rel, irr, out, nblocks);
}

// round 15
// speedup vs baseline: 1.2082x; 1.0723x over previous
#include <cuda_runtime.h>
#include <cstdint>

#define B_SZ 512
#define D_SZ 1024
#define P_SZ 16
#define N_SZ 128
#define ALPHA_F 0.8f
#define NROWS 145                       // per batch: row 0 = tgt, 1..16 = rel, 17..144 = irr
#define TOTAL_ROWS (B_SZ * NROWS)       // 74240
#define TPB 128
#define NWARPS 4
#define BLOCKS_PER_SM 6
#define ROW_BYTES 4096                  // 1024 fp32

__device__ float g_posb[B_SZ];          // zero-init at load; last block resets each run
__device__ float g_negb[B_SZ];
__device__ float g_diag[B_SZ];
__device__ unsigned int g_count = 0;

__device__ __forceinline__ uint32_t smem_u32(const void* p) {
    uint32_t a;
    asm("{ .reg .u64 t; cvta.to.shared.u64 t, %1; cvt.u32.u64 %0, t; }"
        : "=r"(a) : "l"(p));
    return a;
}
__device__ __forceinline__ void mbar_init(uint32_t mbar, uint32_t count) {
    asm volatile("mbarrier.init.shared.b64 [%0], %1;" :: "r"(mbar), "r"(count) : "memory");
}
__device__ __forceinline__ void mbar_expect_tx(uint32_t mbar, uint32_t bytes) {
    asm volatile("mbarrier.arrive.expect_tx.shared.b64 _, [%0], %1;"
                 :: "r"(mbar), "r"(bytes) : "memory");
}
__device__ __forceinline__ void tma_row(uint32_t smem_dst, const float* gmem_src, uint32_t mbar) {
    asm volatile("cp.async.bulk.shared::cta.global.mbarrier::complete_tx::bytes "
                 "[%0], [%1], %2, [%3];"
                 :: "r"(smem_dst), "l"(gmem_src), "r"((uint32_t)ROW_BYTES), "r"(mbar)
                 : "memory");
}
__device__ __forceinline__ void mbar_wait(uint32_t mbar, uint32_t parity) {
    uint32_t done;
    asm volatile(
        "{\n\t.reg .pred p;\n\t"
        "mbarrier.try_wait.parity.acquire.cta.shared::cta.b64 p, [%1], %2;\n\t"
        "selp.b32 %0, 1, 0, p;\n\t}"
        : "=r"(done) : "r"(mbar), "r"(parity) : "memory");
    if (!done) {
        asm volatile(
            "{\n\t.reg .pred P1;\n\t"
            "W_%=:\n\t"
            "mbarrier.try_wait.parity.acquire.cta.shared::cta.b64 P1, [%0], %1, 0x989680;\n\t"
            "@P1 bra.uni D_%=;\n\t"
            "bra.uni W_%=;\n\t"
            "D_%=:\n\t}"
            :: "r"(mbar), "r"(parity) : "memory");
    }
}

// global row index -> gmem pointer (b = g / NROWS, r = g % NROWS)
__device__ __forceinline__ const float*
row_ptr_br(const float* __restrict__ tgt, const float* __restrict__ rel,
           const float* __restrict__ irr, int b, int r)
{
    if (r == 0)         return tgt + (size_t)b * D_SZ;
    else if (r <= P_SZ) return rel + ((size_t)b * P_SZ + (r - 1)) * D_SZ;
    else                return irr + ((size_t)b * N_SZ + (r - 1 - P_SZ)) * D_SZ;
}

__device__ __forceinline__ void
load_sreg(const float* __restrict__ src, int b, int lane,
          float4 (&sreg)[8], float& inv_src)
{
    const float4* sv = reinterpret_cast<const float4*>(src + (size_t)b * D_SZ);
    float ss = 0.f;
    #pragma unroll
    for (int j = 0; j < 8; j++) {
        sreg[j] = __ldg(&sv[j * 32 + lane]);
        ss += sreg[j].x * sreg[j].x + sreg[j].y * sreg[j].y
            + sreg[j].z * sreg[j].z + sreg[j].w * sreg[j].w;
    }
    #pragma unroll
    for (int o = 16; o > 0; o >>= 1) ss += __shfl_xor_sync(0xFFFFFFFFu, ss, o);
    inv_src = rsqrtf(fmaxf(ss, 1e-24f));
}

__global__ void __launch_bounds__(TPB, BLOCKS_PER_SM)
contrastive_loss_kernel(const float* __restrict__ src,
                        const float* __restrict__ tgt,
                        const float* __restrict__ rel,
                        const float* __restrict__ irr,
                        float* __restrict__ out,
                        int nblocks)
{
    __shared__ __align__(16) float4 s_buf[NWARPS][2][ROW_BYTES / 16]; // 32 KB
    __shared__ __align__(8)  unsigned long long s_mbar[NWARPS][2];
    __shared__ float s_red[NWARPS];
    __shared__ int   s_last;

    const int tid  = threadIdx.x;
    const int wid  = tid >> 5;
    const int lane = tid & 31;

    const uint32_t mb0 = smem_u32(&s_mbar[wid][0]);
    const uint32_t mb1 = smem_u32(&s_mbar[wid][1]);
    const uint32_t sb0 = smem_u32(&s_buf[wid][0][0]);
    const uint32_t sb1 = smem_u32(&s_buf[wid][1][0]);

    if (lane == 0) {
        mbar_init(mb0, 1);
        mbar_init(mb1, 1);
        asm volatile("fence.mbarrier_init.release.cluster;" ::: "memory");
    }
    __syncwarp();

    // ---- contiguous slice of the flat row space for this warp ----
    const int nw   = nblocks * NWARPS;
    const int wgid = blockIdx.x * NWARPS + wid;
    const int lo = (int)(((long long)wgid * TOTAL_ROWS) / nw);
    const int hi = (int)(((long long)(wgid + 1) * TOTAL_ROWS) / nw);

    // ---- prime pipeline once for the whole slice ----
    if (lane == 0) {
        if (lo < hi) {
            int pb = lo / NROWS, pr = lo - pb * NROWS;
            mbar_expect_tx(mb0, ROW_BYTES);
            tma_row(sb0, row_ptr_br(tgt, rel, irr, pb, pr), mb0);
        }
        if (lo + 1 < hi) {
            int pb = (lo + 1) / NROWS, pr = (lo + 1) - pb * NROWS;
            mbar_expect_tx(mb1, ROW_BYTES);
            tma_row(sb1, row_ptr_br(tgt, rel, irr, pb, pr), mb1);
        }
    }

    int b = lo / NROWS;
    int r = lo - b * NROWS;
    float4 sreg[8];
    float inv_src;
    load_sreg(src, b, lane, sreg, inv_src);

    float pos = 0.f, neg = 0.f;
    uint32_t ph0 = 0, ph1 = 0;

    for (int g = lo; g < hi; g++) {
        if (r == NROWS) {              // crossed into next batch row
            if (lane == 0) {
                atomicAdd(&g_posb[b], pos);
                atomicAdd(&g_negb[b], neg);
                pos = 0.f; neg = 0.f;
            }
            b++; r = 0;
            load_sreg(src, b, lane, sreg, inv_src);
        }

        const int k = (g - lo) & 1;
        if (k == 0) { mbar_wait(mb0, ph0); ph0 ^= 1u; }
        else        { mbar_wait(mb1, ph1); ph1 ^= 1u; }

        const float4* rv = &s_buf[wid][k][0];
        float dot = 0.f, rss = 0.f;
        #pragma unroll
        for (int j = 0; j < 8; j++) {
            float4 v = rv[j * 32 + lane];
            dot += v.x * sreg[j].x + v.y * sreg[j].y + v.z * sreg[j].z + v.w * sreg[j].w;
            rss += v.x * v.x + v.y * v.y + v.z * v.z + v.w * v.w;
        }

        // refill this stage with row g+2 (all lanes finished reading it)
        if (lane == 0 && g + 2 < hi) {
            int r2 = r + 2, b2 = b;
            if (r2 >= NROWS) { r2 -= NROWS; b2++; }
            const uint32_t mb = k ? mb1 : mb0;
            const uint32_t sb = k ? sb1 : sb0;
            mbar_expect_tx(mb, ROW_BYTES);
            tma_row(sb, row_ptr_br(tgt, rel, irr, b2, r2), mb);
        }

        #pragma unroll
        for (int o = 16; o > 0; o >>= 1) {
            dot += __shfl_xor_sync(0xFFFFFFFFu, dot, o);
            rss += __shfl_xor_sync(0xFFFFFFFFu, rss, o);
        }
        if (lane == 0) {
            float c = dot * inv_src * rsqrtf(fmaxf(rss, 1e-24f));
            if (r == 0)            g_diag[b] = c;          // tgt row: diag
            else if (r <= P_SZ)    pos += __expf(c);
            else                   neg += __expf(c);
        }
        r++;
    }

    if (lane == 0) {
        atomicAdd(&g_posb[b], pos);
        atomicAdd(&g_negb[b], neg);
    }
    __syncthreads();

    if (tid == 0) {
        unsigned old;
        asm volatile("atom.acq_rel.gpu.global.add.u32 %0, [%1], %2;"
                     : "=r"(old)
                     : "l"(&g_count), "r"(1u)
                     : "memory");
        s_last = (old == (unsigned)nblocks - 1u);
    }
    __syncthreads();

    // ---- last block: parallel final loss over 512 batch rows + resets ----
    if (s_last) {
        float acc = 0.f;
        #pragma unroll
        for (int it = 0; it < B_SZ / TPB; it++) {
            int bb = it * TPB + tid;
            float ps = __ldcg(&g_posb[bb]);
            float ns = __ldcg(&g_negb[bb]);
            float dg = __ldcg(&g_diag[bb]);
            float pos_score = 1.f + ps;
            float lp = __logf(pos_score);
            float ln = __logf(pos_score + ns);
            acc += -(ALPHA_F * dg + (1.f - ALPHA_F) * (lp - ln));
            g_posb[bb] = 0.f;          // reset for next graph replay
            g_negb[bb] = 0.f;
        }
        #pragma unroll
        for (int o = 16; o > 0; o >>= 1) acc += __shfl_xor_sync(0xFFFFFFFFu, acc, o);
        if (lane == 0) s_red[wid] = acc;
        __syncthreads();
        if (tid == 0) {
            out[0] = (s_red[0] + s_red[1] + s_red[2] + s_red[3]) * (1.0f / (float)B_SZ);
            g_count = 0;
        }
    }
}

extern "C" void kernel_launch(void* const* d_in, const int* in_sizes, int n_in,
                              void* d_out, int out_size)
{
    const float* src = (const float*)d_in[0];   // [B, D]
    const float* tgt = (const float*)d_in[1];   // [B, D]
    const float* rel = (const float*)d_in[2];   // [B, P, D]
    const float* irr = (const float*)d_in[3];   // [B, N, D]
    float* out = (float*)d_out;

    int sms = 148;
    cudaDeviceGetAttribute(&sms, cudaDevAttrMultiProcessorCount, 0);
    const int nblocks = sms * BLOCKS_PER_SM;    // exactly one wave

    contrastive_loss_kernel<<<nblocks, TPB>>>(src, tgt, rel, irr, out, nblocks);
}

// round 16
// speedup vs baseline: 1.2209x; 1.0105x over previous
#include <cuda_runtime.h>
#include <cstdint>

#define B_SZ 512
#define D_SZ 1024
#define P_SZ 16
#define N_SZ 128
#define ALPHA_F 0.8f
#define NROWS 145                       // per batch: row 0 = tgt, 1..16 = rel, 17..144 = irr
#define TOTAL_ROWS (B_SZ * NROWS)       // 74240
#define TPB 128
#define NWARPS 4
#define BLOCKS_PER_SM 6
#define ROW_BYTES 4096                  // 1024 fp32

__device__ float g_posb[B_SZ];          // zero-init at load; last block resets each run
__device__ float g_negb[B_SZ];
__device__ float g_diag[B_SZ];
__device__ unsigned int g_count = 0;

__device__ __forceinline__ uint32_t smem_u32(const void* p) {
    uint32_t a;
    asm("{ .reg .u64 t; cvta.to.shared.u64 t, %1; cvt.u32.u64 %0, t; }"
        : "=r"(a) : "l"(p));
    return a;
}
__device__ __forceinline__ void mbar_init(uint32_t mbar, uint32_t count) {
    asm volatile("mbarrier.init.shared.b64 [%0], %1;" :: "r"(mbar), "r"(count) : "memory");
}
__device__ __forceinline__ void mbar_expect_tx(uint32_t mbar, uint32_t bytes) {
    asm volatile("mbarrier.arrive.expect_tx.shared.b64 _, [%0], %1;"
                 :: "r"(mbar), "r"(bytes) : "memory");
}
// streaming (read-once) bulk load: L2 evict_first so src rows stay L2-resident
__device__ __forceinline__ uint64_t make_evict_first_policy() {
    uint64_t pol;
    asm("createpolicy.fractional.L2::evict_first.b64 %0, 1.0;" : "=l"(pol));
    return pol;
}
__device__ __forceinline__ void tma_row(uint32_t smem_dst, const float* gmem_src,
                                        uint32_t mbar, uint64_t pol) {
    asm volatile("cp.async.bulk.shared::cta.global.mbarrier::complete_tx::bytes"
                 ".L2::cache_hint [%0], [%1], %2, [%3], %4;"
                 :: "r"(smem_dst), "l"(gmem_src), "r"((uint32_t)ROW_BYTES),
                    "r"(mbar), "l"(pol)
                 : "memory");
}
__device__ __forceinline__ void mbar_wait(uint32_t mbar, uint32_t parity) {
    uint32_t done;
    asm volatile(
        "{\n\t.reg .pred p;\n\t"
        "mbarrier.try_wait.parity.acquire.cta.shared::cta.b64 p, [%1], %2;\n\t"
        "selp.b32 %0, 1, 0, p;\n\t}"
        : "=r"(done) : "r"(mbar), "r"(parity) : "memory");
    if (!done) {
        asm volatile(
            "{\n\t.reg .pred P1;\n\t"
            "W_%=:\n\t"
            "mbarrier.try_wait.parity.acquire.cta.shared::cta.b64 P1, [%0], %1, 0x989680;\n\t"
            "@P1 bra.uni D_%=;\n\t"
            "bra.uni W_%=;\n\t"
            "D_%=:\n\t}"
            :: "r"(mbar), "r"(parity) : "memory");
    }
}

// global row index -> gmem pointer (b = g / NROWS, r = g % NROWS)
__device__ __forceinline__ const float*
row_ptr_br(const float* __restrict__ tgt, const float* __restrict__ rel,
           const float* __restrict__ irr, int b, int r)
{
    if (r == 0)         return tgt + (size_t)b * D_SZ;
    else if (r <= P_SZ) return rel + ((size_t)b * P_SZ + (r - 1)) * D_SZ;
    else                return irr + ((size_t)b * N_SZ + (r - 1 - P_SZ)) * D_SZ;
}

__device__ __forceinline__ void
load_sreg(const float* __restrict__ src, int b, int lane,
          float4 (&sreg)[8], float& inv_src)
{
    const float4* sv = reinterpret_cast<const float4*>(src + (size_t)b * D_SZ);
    float ss = 0.f;
    #pragma unroll
    for (int j = 0; j < 8; j++) {
        sreg[j] = __ldg(&sv[j * 32 + lane]);
        ss += sreg[j].x * sreg[j].x + sreg[j].y * sreg[j].y
            + sreg[j].z * sreg[j].z + sreg[j].w * sreg[j].w;
    }
    #pragma unroll
    for (int o = 16; o > 0; o >>= 1) ss += __shfl_xor_sync(0xFFFFFFFFu, ss, o);
    inv_src = rsqrtf(fmaxf(ss, 1e-24f));
}

__global__ void __launch_bounds__(TPB, BLOCKS_PER_SM)
contrastive_loss_kernel(const float* __restrict__ src,
                        const float* __restrict__ tgt,
                        const float* __restrict__ rel,
                        const float* __restrict__ irr,
                        float* __restrict__ out,
                        int nblocks)
{
    __shared__ __align__(16) float4 s_buf[NWARPS][2][ROW_BYTES / 16]; // 32 KB
    __shared__ __align__(8)  unsigned long long s_mbar[NWARPS][2];
    __shared__ float s_red[NWARPS];
    __shared__ int   s_last;

    const int tid  = threadIdx.x;
    const int wid  = tid >> 5;
    const int lane = tid & 31;

    const uint32_t mb0 = smem_u32(&s_mbar[wid][0]);
    const uint32_t mb1 = smem_u32(&s_mbar[wid][1]);
    const uint32_t sb0 = smem_u32(&s_buf[wid][0][0]);
    const uint32_t sb1 = smem_u32(&s_buf[wid][1][0]);
    const uint64_t pol = make_evict_first_policy();

    if (lane == 0) {
        mbar_init(mb0, 1);
        mbar_init(mb1, 1);
        asm volatile("fence.mbarrier_init.release.cluster;" ::: "memory");
    }
    __syncwarp();

    // ---- contiguous slice of the flat row space for this warp ----
    const int nw   = nblocks * NWARPS;
    const int wgid = blockIdx.x * NWARPS + wid;
    const int lo = (int)(((long long)wgid * TOTAL_ROWS) / nw);
    const int hi = (int)(((long long)(wgid + 1) * TOTAL_ROWS) / nw);

    // ---- prime pipeline once for the whole slice ----
    if (lane == 0) {
        if (lo < hi) {
            int pb = lo / NROWS, pr = lo - pb * NROWS;
            mbar_expect_tx(mb0, ROW_BYTES);
            tma_row(sb0, row_ptr_br(tgt, rel, irr, pb, pr), mb0, pol);
        }
        if (lo + 1 < hi) {
            int pb = (lo + 1) / NROWS, pr = (lo + 1) - pb * NROWS;
            mbar_expect_tx(mb1, ROW_BYTES);
            tma_row(sb1, row_ptr_br(tgt, rel, irr, pb, pr), mb1, pol);
        }
    }

    int b = lo / NROWS;
    int r = lo - b * NROWS;
    float4 sreg[8];
    float inv_src;
    load_sreg(src, b, lane, sreg, inv_src);

    float pos = 0.f, neg = 0.f;
    uint32_t ph0 = 0, ph1 = 0;

    for (int g = lo; g < hi; g++) {
        if (r == NROWS) {              // crossed into next batch row
            if (lane == 0) {
                atomicAdd(&g_posb[b], pos);
                atomicAdd(&g_negb[b], neg);
                pos = 0.f; neg = 0.f;
            }
            b++; r = 0;
            load_sreg(src, b, lane, sreg, inv_src);
        }

        const int k = (g - lo) & 1;
        if (k == 0) { mbar_wait(mb0, ph0); ph0 ^= 1u; }
        else        { mbar_wait(mb1, ph1); ph1 ^= 1u; }

        const float4* rv = &s_buf[wid][k][0];
        float dot = 0.f, rss = 0.f;
        #pragma unroll
        for (int j = 0; j < 8; j++) {
            float4 v = rv[j * 32 + lane];
            dot += v.x * sreg[j].x + v.y * sreg[j].y + v.z * sreg[j].z + v.w * sreg[j].w;
            rss += v.x * v.x + v.y * v.y + v.z * v.z + v.w * v.w;
        }

        // refill this stage with row g+2 (all lanes finished reading it)
        if (lane == 0 && g + 2 < hi) {
            int r2 = r + 2, b2 = b;
            if (r2 >= NROWS) { r2 -= NROWS; b2++; }
            const uint32_t mb = k ? mb1 : mb0;
            const uint32_t sb = k ? sb1 : sb0;
            mbar_expect_tx(mb, ROW_BYTES);
            tma_row(sb, row_ptr_br(tgt, rel, irr, b2, r2), mb, pol);
        }

        #pragma unroll
        for (int o = 16; o > 0; o >>= 1) {
            dot += __shfl_xor_sync(0xFFFFFFFFu, dot, o);
            rss += __shfl_xor_sync(0xFFFFFFFFu, rss, o);
        }
        if (lane == 0) {
            float c = dot * inv_src * rsqrtf(fmaxf(rss, 1e-24f));
            if (r == 0)            g_diag[b] = c;          // tgt row: diag
            else if (r <= P_SZ)    pos += __expf(c);
            else                   neg += __expf(c);
        }
        r++;
    }

    if (lane == 0) {
        atomicAdd(&g_posb[b], pos);
        atomicAdd(&g_negb[b], neg);
    }
    __syncthreads();

    if (tid == 0) {
        unsigned old;
        asm volatile("atom.acq_rel.gpu.global.add.u32 %0, [%1], %2;"
                     : "=r"(old)
                     : "l"(&g_count), "r"(1u)
                     : "memory");
        s_last = (old == (unsigned)nblocks - 1u);
    }
    __syncthreads();

    // ---- last block: parallel final loss over 512 batch rows + resets ----
    if (s_last) {
        float acc = 0.f;
        #pragma unroll
        for (int it = 0; it < B_SZ / TPB; it++) {
            int bb = it * TPB + tid;
            float ps = __ldcg(&g_posb[bb]);
            float ns = __ldcg(&g_negb[bb]);
            float dg = __ldcg(&g_diag[bb]);
            float pos_score = 1.f + ps;
            float lp = __logf(pos_score);
            float ln = __logf(pos_score + ns);
            acc += -(ALPHA_F * dg + (1.f - ALPHA_F) * (lp - ln));
            g_posb[bb] = 0.f;          // reset for next graph replay
            g_negb[bb] = 0.f;
        }
        #pragma unroll
        for (int o = 16; o > 0; o >>= 1) acc += __shfl_xor_sync(0xFFFFFFFFu, acc, o);
        if (lane == 0) s_red[wid] = acc;
        __syncthreads();
        if (tid == 0) {
            out[0] = (s_red[0] + s_red[1] + s_red[2] + s_red[3]) * (1.0f / (float)B_SZ);
            g_count = 0;
        }
    }
}

extern "C" void kernel_launch(void* const* d_in, const int* in_sizes, int n_in,
                              void* d_out, int out_size)
{
    const float* src = (const float*)d_in[0];   // [B, D]
    const float* tgt = (const float*)d_in[1];   // [B, D]
    const float* rel = (const float*)d_in[2];   // [B, P, D]
    const float* irr = (const float*)d_in[3];   // [B, N, D]
    float* out = (float*)d_out;

    int sms = 148;
    cudaDeviceGetAttribute(&sms, cudaDevAttrMultiProcessorCount, 0);
    const int nblocks = sms * BLOCKS_PER_SM;    // exactly one wave

    contrastive_loss_kernel<<<nblocks, TPB>>>(src, tgt, rel, irr, out, nblocks);
}